// round 16
// baseline (speedup 1.0000x reference)
#include <cuda_runtime.h>
#include <cuda_fp16.h>
#include <math_constants.h>
#include <cstdint>

// Problem constants
#define BB   2
#define SS   2048
#define DIM  1536
#define NHD  16
#define HD   96
#define NTOK (BB*SS)            // 4096
#define ATT_SCALE 0.10206207261596575f   // 1/sqrt(96)

// Scratch (device globals; allocation-free)
__device__ float g_q[NTOK * DIM];
__device__ float g_k[NTOK * DIM];
__device__ float g_v[NTOK * DIM];

__device__ __half g_h_hi[NTOK * DIM];
__device__ __half g_ao_hi[NTOK * DIM];
__device__ __half g_wq_hi[DIM * DIM];
__device__ __half g_wk_hi[DIM * DIM];
__device__ __half g_wv_hi[DIM * DIM];
__device__ __half g_wo_hi[DIM * DIM];

// Post-RoPE fp16 (q rounded + prescaled by ATT_SCALE; k rounded), f16x2 words
__device__ unsigned int g_qhi[NTOK * DIM / 2];
__device__ unsigned int g_khi[NTOK * DIM / 2];
// V transposed per (b,h): [32][96][2048] fp16 -> words [32][96][1024]
__device__ unsigned int g_vthi[32 * 96 * 1024];

// ---------------------------------------------------------------------------
// helpers
// ---------------------------------------------------------------------------
__device__ __forceinline__ unsigned int pack_f16x2(float lo, float hi) {
    unsigned int r;
    asm("cvt.rn.f16x2.f32 %0, %1, %2;" : "=r"(r) : "f"(hi), "f"(lo));
    return r;
}
__device__ __forceinline__ unsigned int smem_u32(const void* p) {
    unsigned int a;
    asm("{ .reg .u64 t; cvta.to.shared.u64 t, %1; cvt.u32.u64 %0, t; }"
        : "=r"(a) : "l"(p));
    return a;
}

#define MMA_F16(d, a, b) \
  asm volatile("mma.sync.aligned.m16n8k16.row.col.f32.f16.f16.f32 " \
    "{%0,%1,%2,%3}, {%4,%5,%6,%7}, {%8,%9}, {%0,%1,%2,%3};" \
    : "+f"(d[0]), "+f"(d[1]), "+f"(d[2]), "+f"(d[3]) \
    : "r"(a[0]), "r"(a[1]), "r"(a[2]), "r"(a[3]), "r"(b[0]), "r"(b[1]))

#define LDSM4(r0, r1, r2, r3, addr) \
  asm volatile("ldmatrix.sync.aligned.m8n8.x4.shared.b16 {%0,%1,%2,%3}, [%4];" \
    : "=r"(r0), "=r"(r1), "=r"(r2), "=r"(r3) : "r"(addr))

#define CPA16(dst_s, src_g) \
  asm volatile("cp.async.ca.shared.global [%0], [%1], 16;" :: "r"(dst_s), "l"(src_g))
#define CPA16CG(dst_s, src_g) \
  asm volatile("cp.async.cg.shared.global [%0], [%1], 16;" :: "r"(dst_s), "l"(src_g))
#define CP_COMMIT() asm volatile("cp.async.commit_group;" ::: "memory")
#define CP_WAIT0()  asm volatile("cp.async.wait_group 0;" ::: "memory")
#define CP_WAIT1()  asm volatile("cp.async.wait_group 1;" ::: "memory")

// ---------------------------------------------------------------------------
// fp32 -> fp16 round, single tensor (h / activations)
// ---------------------------------------------------------------------------
__global__ void __launch_bounds__(256) round_fp16_kernel(
    const float4* __restrict__ x, unsigned int* __restrict__ hi, int n4)
{
    int i = blockIdx.x * 256 + threadIdx.x;
    if (i >= n4) return;
    float4 v = x[i];
    hi[i*2]   = pack_f16x2(v.x, v.y);
    hi[i*2+1] = pack_f16x2(v.z, v.w);
}

// fp32 -> fp16 round, 4 weight matrices in one launch (grid.y selects)
struct RoundPtrs {
    const float4 *x0, *x1, *x2, *x3;
    unsigned int *o0, *o1, *o2, *o3;
};
__global__ void __launch_bounds__(256) round4_fp16_kernel(RoundPtrs P, int n4)
{
    int i = blockIdx.x * 256 + threadIdx.x;
    if (i >= n4) return;
    int z = blockIdx.y;
    const float4* x = (z == 0) ? P.x0 : (z == 1) ? P.x1 : (z == 2) ? P.x2 : P.x3;
    unsigned int* hi = (z == 0) ? P.o0 : (z == 1) ? P.o1 : (z == 2) ? P.o2 : P.o3;
    float4 v = x[i];
    hi[i*2]   = pack_f16x2(v.x, v.y);
    hi[i*2+1] = pack_f16x2(v.z, v.w);
}

// ---------------------------------------------------------------------------
// ldmatrix tensor-core GEMM: C[m][n] = sum_k A[m][k] * W[n][k]
// CTA 128x128, BK=64, 256 threads, warp 64x32, fp16 hi-only (1 MMA/site).
// 3-stage cp.async pipeline. grid.z = QKV fusion.
// ---------------------------------------------------------------------------
#define GL_STAGE 32768     // 2 tiles x 128 rows x 128B (Ahi, Bhi)
#define GL_SMEM  (3 * GL_STAGE)
#define GL_NC    (DIM / 64)   // 24

struct GemmPtrs {
    const __half *b0, *b1, *b2;
    float *c0, *c1, *c2;
};

__device__ __forceinline__ void gl_prefetch(
    unsigned int stage_base,
    const __half* __restrict__ a_h, const __half* __restrict__ b_h,
    int tid, int koff)
{
    #pragma unroll
    for (int t = 0; t < 2; t++) {
        const __half* s = (t == 0) ? a_h : b_h;
        #pragma unroll
        for (int i = 0; i < 4; i++) {
            int w = tid + 256 * i;          // 0..1023
            int r = w >> 3, cc = w & 7;     // row, 16B chunk
            unsigned int off = r * 128 + cc * 16;
            unsigned int dst = stage_base + t * 16384 + (off ^ ((off >> 3) & 0x70));
            CPA16CG(dst, s + (size_t)r * DIM + koff + cc * 8);
        }
    }
    CP_COMMIT();
}

__global__ void __launch_bounds__(256, 2) gemm_ldsm_nt(
    const __half* __restrict__ Ahi, GemmPtrs P)
{
    extern __shared__ char smraw[];
    const unsigned int sbase = smem_u32(smraw);
    const int tid  = threadIdx.x;
    const int lane = tid & 31;
    const int warp = tid >> 5;
    const int warp_m = warp >> 2;    // 0..1
    const int warp_n = warp & 3;     // 0..3
    const int row0 = blockIdx.y * 128;
    const int col0 = blockIdx.x * 128;
    const int z = blockIdx.z;

    const __half* Whi = (z == 0) ? P.b0 : (z == 1) ? P.b1 : P.b2;
    float* C = (z == 0) ? P.c0 : (z == 1) ? P.c1 : P.c2;

    const __half* a_h = Ahi + (size_t)row0 * DIM;
    const __half* b_h = Whi + (size_t)col0 * DIM;

    // ldmatrix lane address components
    const int g = lane >> 3, j = lane & 7;
    const unsigned int rA = warp_m * 64 + (g & 1) * 8 + j;   // + mbl*16
    const unsigned int cA = (g >> 1) * 16;                   // + kc*32
    const unsigned int rB = warp_n * 32 + (g >> 1) * 8 + j;  // + nb2*16
    const unsigned int cB = (g & 1) * 16;

    float acc[4][4][4] = {};    // [mbl][nbl][reg]

    gl_prefetch(sbase,            a_h, b_h, tid, 0);
    gl_prefetch(sbase + GL_STAGE, a_h, b_h, tid, 64);

    int sidx = 0;   // stage of current chunk c
    for (int c = 0; c < GL_NC; c++) {
        if (c + 1 < GL_NC) CP_WAIT1(); else CP_WAIT0();
        __syncthreads();
        if (c + 2 < GL_NC) {
            int ns = sidx + 2; if (ns >= 3) ns -= 3;
            gl_prefetch(sbase + ns * GL_STAGE, a_h, b_h, tid, (c + 2) * 64);
        }

        const unsigned int stb = sbase + sidx * GL_STAGE;

        #pragma unroll
        for (int kc = 0; kc < 4; kc++) {
            unsigned int ah[4][4];
            #pragma unroll
            for (int mbl = 0; mbl < 4; mbl++) {
                unsigned int off = (rA + mbl * 16) * 128 + cA + kc * 32;
                unsigned int sw = off ^ ((off >> 3) & 0x70);
                LDSM4(ah[mbl][0], ah[mbl][1], ah[mbl][2], ah[mbl][3], stb + sw);
            }
            unsigned int bh[4][2];
            #pragma unroll
            for (int nb2 = 0; nb2 < 2; nb2++) {
                unsigned int off = (rB + nb2 * 16) * 128 + cB + kc * 32;
                unsigned int sw = off ^ ((off >> 3) & 0x70);
                unsigned int r0, r1, r2, r3;
                LDSM4(r0, r1, r2, r3, stb + 16384 + sw);
                bh[2*nb2][0] = r0; bh[2*nb2][1] = r1;
                bh[2*nb2+1][0] = r2; bh[2*nb2+1][1] = r3;
            }
            #pragma unroll
            for (int mbl = 0; mbl < 4; mbl++)
                #pragma unroll
                for (int nbl = 0; nbl < 4; nbl++)
                    MMA_F16(acc[mbl][nbl], ah[mbl], bh[nbl]);
        }
        sidx++; if (sidx >= 3) sidx = 0;
    }

    #pragma unroll
    for (int mbl = 0; mbl < 4; mbl++) {
        int mrow = row0 + warp_m * 64 + mbl * 16 + (lane >> 2);
        #pragma unroll
        for (int nbl = 0; nbl < 4; nbl++) {
            int ncol = col0 + warp_n * 32 + nbl * 8 + (lane & 3) * 2;
            float2 v0 = make_float2(acc[mbl][nbl][0], acc[mbl][nbl][1]);
            float2 v1 = make_float2(acc[mbl][nbl][2], acc[mbl][nbl][3]);
            *(float2*)&C[(size_t)mrow * DIM + ncol]       = v0;
            *(float2*)&C[(size_t)(mrow + 8) * DIM + ncol] = v1;
        }
    }
}

// ---------------------------------------------------------------------------
// 128x64 tile GEMM variant for the O-projection, 3-stage pipeline.
// ---------------------------------------------------------------------------
#define G64_STAGE 24576    // Ahi 16KB + Bhi 8KB
#define G64_SMEM  (3 * G64_STAGE)

__device__ __forceinline__ void g64_prefetch(
    unsigned int stage_base,
    const __half* __restrict__ a_h, const __half* __restrict__ b_h,
    int tid, int koff)
{
    #pragma unroll
    for (int i = 0; i < 4; i++) {
        int w = tid + 256 * i;
        int r = w >> 3, cc = w & 7;
        unsigned int off = r * 128 + cc * 16;
        unsigned int dst = stage_base + (off ^ ((off >> 3) & 0x70));
        CPA16CG(dst, a_h + (size_t)r * DIM + koff + cc * 8);
    }
    #pragma unroll
    for (int i = 0; i < 2; i++) {
        int w = tid + 256 * i;
        int r = w >> 3, cc = w & 7;
        unsigned int off = r * 128 + cc * 16;
        unsigned int dst = stage_base + 16384 + (off ^ ((off >> 3) & 0x70));
        CPA16CG(dst, b_h + (size_t)r * DIM + koff + cc * 8);
    }
    CP_COMMIT();
}

__global__ void __launch_bounds__(256) gemm_ldsm_nt64(
    const __half* __restrict__ Ahi, const __half* __restrict__ Whi,
    float* __restrict__ C)
{
    extern __shared__ char smraw[];
    const unsigned int sbase = smem_u32(smraw);
    const int tid  = threadIdx.x;
    const int lane = tid & 31;
    const int warp = tid >> 5;
    const int warp_m = warp >> 2;
    const int warp_n = warp & 3;
    const int row0 = blockIdx.y * 128;
    const int col0 = blockIdx.x * 64;

    const __half* a_h = Ahi + (size_t)row0 * DIM;
    const __half* b_h = Whi + (size_t)col0 * DIM;

    const int g = lane >> 3, j = lane & 7;
    const unsigned int rA = warp_m * 64 + (g & 1) * 8 + j;
    const unsigned int cA = (g >> 1) * 16;
    const unsigned int rB = warp_n * 16 + (g >> 1) * 8 + j;
    const unsigned int cB = (g & 1) * 16;

    float acc[4][2][4] = {};

    g64_prefetch(sbase,             a_h, b_h, tid, 0);
    g64_prefetch(sbase + G64_STAGE, a_h, b_h, tid, 64);

    int sidx = 0;
    for (int c = 0; c < GL_NC; c++) {
        if (c + 1 < GL_NC) CP_WAIT1(); else CP_WAIT0();
        __syncthreads();
        if (c + 2 < GL_NC) {
            int ns = sidx + 2; if (ns >= 3) ns -= 3;
            g64_prefetch(sbase + ns * G64_STAGE, a_h, b_h, tid, (c + 2) * 64);
        }

        const unsigned int stb = sbase + sidx * G64_STAGE;

        #pragma unroll
        for (int kc = 0; kc < 4; kc++) {
            unsigned int ah[4][4];
            #pragma unroll
            for (int mbl = 0; mbl < 4; mbl++) {
                unsigned int off = (rA + mbl * 16) * 128 + cA + kc * 32;
                unsigned int sw = off ^ ((off >> 3) & 0x70);
                LDSM4(ah[mbl][0], ah[mbl][1], ah[mbl][2], ah[mbl][3], stb + sw);
            }
            unsigned int bh[2][2];
            {
                unsigned int off = rB * 128 + cB + kc * 32;
                unsigned int sw = off ^ ((off >> 3) & 0x70);
                unsigned int r0, r1, r2, r3;
                LDSM4(r0, r1, r2, r3, stb + 16384 + sw);
                bh[0][0] = r0; bh[0][1] = r1;
                bh[1][0] = r2; bh[1][1] = r3;
            }
            #pragma unroll
            for (int mbl = 0; mbl < 4; mbl++)
                #pragma unroll
                for (int nbl = 0; nbl < 2; nbl++)
                    MMA_F16(acc[mbl][nbl], ah[mbl], bh[nbl]);
        }
        sidx++; if (sidx >= 3) sidx = 0;
    }

    #pragma unroll
    for (int mbl = 0; mbl < 4; mbl++) {
        int mrow = row0 + warp_m * 64 + mbl * 16 + (lane >> 2);
        #pragma unroll
        for (int nbl = 0; nbl < 2; nbl++) {
            int ncol = col0 + warp_n * 16 + nbl * 8 + (lane & 3) * 2;
            float2 v0 = make_float2(acc[mbl][nbl][0], acc[mbl][nbl][1]);
            float2 v1 = make_float2(acc[mbl][nbl][2], acc[mbl][nbl][3]);
            *(float2*)&C[(size_t)mrow * DIM + ncol]       = v0;
            *(float2*)&C[(size_t)(mrow + 8) * DIM + ncol] = v1;
        }
    }
}

// ---------------------------------------------------------------------------
// RoPE + fp16: q rounded (prescaled), k rounded -> f16x2 words.
// ---------------------------------------------------------------------------
__global__ void __launch_bounds__(256) rope_split_kernel(
    const float* __restrict__ q, const float* __restrict__ k,
    const int* __restrict__ xyz,
    unsigned int* __restrict__ qhi, unsigned int* __restrict__ khi)
{
    int idx = blockIdx.x * 256 + threadIdx.x;   // NTOK*16*3*8
    int j2 = idx & 7;
    int p  = (idx >> 3) % 3;
    int th = idx / 24;
    int h  = th & 15;
    int t  = th >> 4;
    if (t >= NTOK) return;

    float pos = (float)xyz[t * 3 + p];
    const float c = 0.83048202372184058696f;   // log2(10000)/16
    int j0 = 2 * j2;
    float s0, c0, s1, c1;
    sincosf(pos * exp2f(-(float)j0 * c), &s0, &c0);
    sincosf(pos * exp2f(-(float)(j0 + 1) * c), &s1, &c1);

    int base = t * DIM + h * HD + p * 32 + j0;
    int wbase = t * (DIM/2) + h * (HD/2) + p * 16 + j2;

    {
        float2 a = *(const float2*)&q[base];
        float2 b = *(const float2*)&q[base + 16];
        float o1x = (a.x * c0 - b.x * s0) * ATT_SCALE;
        float o1y = (a.y * c1 - b.y * s1) * ATT_SCALE;
        float o2x = (b.x * c0 + a.x * s0) * ATT_SCALE;
        float o2y = (b.y * c1 + a.y * s1) * ATT_SCALE;
        qhi[wbase]     = pack_f16x2(o1x, o1y);
        qhi[wbase + 8] = pack_f16x2(o2x, o2y);
    }
    {
        float2 a = *(const float2*)&k[base];
        float2 b = *(const float2*)&k[base + 16];
        float o1x = a.x * c0 - b.x * s0;
        float o1y = a.y * c1 - b.y * s1;
        float o2x = b.x * c0 + a.x * s0;
        float o2y = b.y * c1 + a.y * s1;
        khi[wbase]     = pack_f16x2(o1x, o1y);
        khi[wbase + 8] = pack_f16x2(o2x, o2y);
    }
}

// ---------------------------------------------------------------------------
// V transpose + fp16 round (256 threads)
// ---------------------------------------------------------------------------
__global__ void __launch_bounds__(256) vtrans_kernel(
    const float* __restrict__ v, unsigned int* __restrict__ vthi)
{
    __shared__ float sm[96 * 65];
    const int tid = threadIdx.x;
    const int bh = blockIdx.y;
    const int b = bh >> 4, h = bh & 15;
    const int s0 = blockIdx.x * 64;

    {
        int s = tid >> 2, qtr = tid & 3;
        const float* src = v + (size_t)(b * SS + s0 + s) * DIM + h * HD + qtr * 24;
        #pragma unroll
        for (int i = 0; i < 6; i++) {
            float4 x = *(const float4*)(src + i * 4);
            int d = qtr * 24 + i * 4;
            sm[(d + 0) * 65 + s] = x.x;
            sm[(d + 1) * 65 + s] = x.y;
            sm[(d + 2) * 65 + s] = x.z;
            sm[(d + 3) * 65 + s] = x.w;
        }
    }
    __syncthreads();

    #pragma unroll
    for (int i = 0; i < 12; i++) {
        int w = tid + 256 * i;
        int d = w >> 5, j = w & 31;
        float f0 = sm[d * 65 + 2 * j];
        float f1 = sm[d * 65 + 2 * j + 1];
        vthi[(size_t)(bh * 96 + d) * 1024 + (s0 >> 1) + j] = pack_f16x2(f0, f1);
    }
}

// ---------------------------------------------------------------------------
// MMA flash attention (fp16: Q/K/V/P all rounded). 64 q-rows per CTA,
// 128 threads (4 warps), 2 CTAs/SM. Output: aohi only.
// ---------------------------------------------------------------------------
#define AKHI 0
#define AVHI 3328
#define ABUF 6784
#define ATT_SMEM_BYTES (2 * ABUF * 4)

__global__ void __launch_bounds__(128, 2) attn_mma_kernel(
    const unsigned int* __restrict__ qhi,
    const unsigned int* __restrict__ khi,
    const unsigned int* __restrict__ vthi,
    unsigned int* __restrict__ aohi)
{
    extern __shared__ unsigned int smw[];
    unsigned int sbase = smem_u32(smw);

    const int tid  = threadIdx.x;
    const int lane = tid & 31;
    const int warp = tid >> 5;
    const int qt = blockIdx.x;
    const int bh = blockIdx.y;
    const int b = bh >> 4, h = bh & 15;
    const int h48 = h * 48;
    const int qrow0 = b * SS + qt * 64;

    unsigned int qh[6][4];
    {
        const unsigned int* qhg = qhi + (size_t)qrow0 * 768 + h48;
        int r0 = warp * 16 + (lane >> 2);
        #pragma unroll
        for (int kb = 0; kb < 6; kb++) {
            int w0 = kb * 8 + (lane & 3);
            qh[kb][0] = qhg[(size_t)r0 * 768 + w0];
            qh[kb][1] = qhg[(size_t)(r0 + 8) * 768 + w0];
            qh[kb][2] = qhg[(size_t)r0 * 768 + w0 + 4];
            qh[kb][3] = qhg[(size_t)(r0 + 8) * 768 + w0 + 4];
        }
    }

    float O[12][4];
    #pragma unroll
    for (int nb = 0; nb < 12; nb++)
        #pragma unroll
        for (int i = 0; i < 4; i++) O[nb][i] = 0.0f;
    float m0 = -CUDART_INF_F, m1 = -CUDART_INF_F, l0 = 0.0f, l1 = 0.0f;

#define PREFETCH(bi, ktv)                                                      \
    {                                                                          \
        int ktok = b * SS + (ktv) * 64;                                        \
        _Pragma("unroll")                                                      \
        for (int i = 0; i < 6; i++) {                                          \
            int cc = tid + 128 * i;                                            \
            int key = cc / 12, j = cc - key * 12;                              \
            unsigned int dw = ((bi) * ABUF + key * 52 + j * 4);                \
            CPA16(sbase + dw * 4,                                              \
                  khi + (size_t)(ktok + key) * 768 + h48 + j * 4);             \
        }                                                                      \
        _Pragma("unroll")                                                      \
        for (int i = 0; i < 6; i++) {                                          \
            int cc = tid + 128 * i;                                            \
            int d = cc >> 3, j = cc & 7;                                       \
            unsigned int dw = ((bi) * ABUF + AVHI + d * 36 + j * 4);           \
            CPA16(sbase + dw * 4,                                              \
                  vthi + (size_t)(bh * 96 + d) * 1024 + (ktv) * 32 + j * 4);   \
        }                                                                      \
        CP_COMMIT();                                                           \
    }

    PREFETCH(0, 0);

    for (int kt = 0; kt < SS / 64; kt++) {
        CP_WAIT0();
        __syncthreads();
        if (kt + 1 < SS / 64) PREFETCH((kt + 1) & 1, kt + 1);

        const unsigned int* kh = smw + (kt & 1) * ABUF + AKHI;
        const unsigned int* vh = smw + (kt & 1) * ABUF + AVHI;

        float S[8][4];
        #pragma unroll
        for (int nb = 0; nb < 8; nb++) {
            #pragma unroll
            for (int i = 0; i < 4; i++) S[nb][i] = 0.0f;
            int key = nb * 8 + (lane >> 2);
            #pragma unroll
            for (int kb = 0; kb < 6; kb++) {
                int w0 = kb * 8 + (lane & 3);
                unsigned int bhf[2] = { kh[key * 52 + w0], kh[key * 52 + w0 + 4] };
                MMA_F16(S[nb], qh[kb], bhf);
            }
        }

        float ml0 = -CUDART_INF_F, ml1 = -CUDART_INF_F;
        #pragma unroll
        for (int nb = 0; nb < 8; nb++) {
            ml0 = fmaxf(ml0, fmaxf(S[nb][0], S[nb][1]));
            ml1 = fmaxf(ml1, fmaxf(S[nb][2], S[nb][3]));
        }
        ml0 = fmaxf(ml0, __shfl_xor_sync(0xffffffffu, ml0, 1));
        ml0 = fmaxf(ml0, __shfl_xor_sync(0xffffffffu, ml0, 2));
        ml1 = fmaxf(ml1, __shfl_xor_sync(0xffffffffu, ml1, 1));
        ml1 = fmaxf(ml1, __shfl_xor_sync(0xffffffffu, ml1, 2));
        float mn0 = fmaxf(m0, ml0), mn1 = fmaxf(m1, ml1);
        float sc0 = __expf(m0 - mn0), sc1 = __expf(m1 - mn1);
        float r0 = 0.0f, r1 = 0.0f;
        #pragma unroll
        for (int nb = 0; nb < 8; nb++) {
            S[nb][0] = __expf(S[nb][0] - mn0);
            S[nb][1] = __expf(S[nb][1] - mn0);
            S[nb][2] = __expf(S[nb][2] - mn1);
            S[nb][3] = __expf(S[nb][3] - mn1);
            r0 += S[nb][0] + S[nb][1];
            r1 += S[nb][2] + S[nb][3];
        }
        r0 += __shfl_xor_sync(0xffffffffu, r0, 1);
        r0 += __shfl_xor_sync(0xffffffffu, r0, 2);
        r1 += __shfl_xor_sync(0xffffffffu, r1, 1);
        r1 += __shfl_xor_sync(0xffffffffu, r1, 2);
        l0 = l0 * sc0 + r0;  m0 = mn0;
        l1 = l1 * sc1 + r1;  m1 = mn1;

        #pragma unroll
        for (int nb = 0; nb < 12; nb++) {
            O[nb][0] *= sc0; O[nb][1] *= sc0;
            O[nb][2] *= sc1; O[nb][3] *= sc1;
        }

        // P: C-frag -> fp16 A-frag (hi only)
        unsigned int ph[4][4];
        #pragma unroll
        for (int kb = 0; kb < 4; kb++) {
            float f[8] = { S[2*kb][0], S[2*kb][1], S[2*kb][2], S[2*kb][3],
                           S[2*kb+1][0], S[2*kb+1][1], S[2*kb+1][2], S[2*kb+1][3] };
            #pragma unroll
            for (int rgp = 0; rgp < 4; rgp++)
                ph[kb][rgp] = pack_f16x2(f[2*rgp], f[2*rgp+1]);
        }

        #pragma unroll
        for (int nb = 0; nb < 12; nb++) {
            int d = nb * 8 + (lane >> 2);
            #pragma unroll
            for (int kb = 0; kb < 4; kb++) {
                int w0 = kb * 8 + (lane & 3);
                unsigned int bhf[2] = { vh[d * 36 + w0], vh[d * 36 + w0 + 4] };
                MMA_F16(O[nb], ph[kb], bhf);
            }
        }
    }

    float li0 = 1.0f / l0, li1 = 1.0f / l1;
    int tok0 = qrow0 + warp * 16 + (lane >> 2);
    int tok1 = tok0 + 8;
    #pragma unroll
    for (int nb = 0; nb < 12; nb++) {
        int wd = nb * 4 + (lane & 3);
        aohi[(size_t)tok0 * 768 + h48 + wd] =
            pack_f16x2(O[nb][0] * li0, O[nb][1] * li0);
        aohi[(size_t)tok1 * 768 + h48 + wd] =
            pack_f16x2(O[nb][2] * li1, O[nb][3] * li1);
    }
}

// ---------------------------------------------------------------------------
extern "C" void kernel_launch(void* const* d_in, const int* in_sizes, int n_in,
                              void* d_out, int out_size)
{
    const int*   xyz = (const int*)d_in[0];
    const float* h   = (const float*)d_in[1];
    const float* wq  = (const float*)d_in[2];
    const float* wk  = (const float*)d_in[3];
    const float* wv  = (const float*)d_in[4];
    const float* wo  = (const float*)d_in[5];
    float* out = (float*)d_out;

    float *pq, *pk, *pv;
    cudaGetSymbolAddress((void**)&pq,  g_q);
    cudaGetSymbolAddress((void**)&pk,  g_k);
    cudaGetSymbolAddress((void**)&pv,  g_v);

    __half *hh, *aoh, *wqh, *wkh, *wvh, *woh;
    cudaGetSymbolAddress((void**)&hh,  g_h_hi);
    cudaGetSymbolAddress((void**)&aoh, g_ao_hi);
    cudaGetSymbolAddress((void**)&wqh, g_wq_hi);
    cudaGetSymbolAddress((void**)&wkh, g_wk_hi);
    cudaGetSymbolAddress((void**)&wvh, g_wv_hi);
    cudaGetSymbolAddress((void**)&woh, g_wo_hi);

    unsigned int *uqh, *ukh, *uvh;
    cudaGetSymbolAddress((void**)&uqh, g_qhi);
    cudaGetSymbolAddress((void**)&ukh, g_khi);
    cudaGetSymbolAddress((void**)&uvh, g_vthi);

    const int nH4 = NTOK * DIM / 4;
    const int nW4 = DIM * DIM / 4;
    round_fp16_kernel<<<(nH4 + 255)/256, 256>>>((const float4*)h,
        (unsigned int*)hh, nH4);

    RoundPtrs Rp;
    Rp.x0 = (const float4*)wq; Rp.o0 = (unsigned int*)wqh;
    Rp.x1 = (const float4*)wk; Rp.o1 = (unsigned int*)wkh;
    Rp.x2 = (const float4*)wv; Rp.o2 = (unsigned int*)wvh;
    Rp.x3 = (const float4*)wo; Rp.o3 = (unsigned int*)woh;
    dim3 rg((nW4 + 255)/256, 4);
    round4_fp16_kernel<<<rg, 256>>>(Rp, nW4);

    cudaFuncSetAttribute(gemm_ldsm_nt, cudaFuncAttributeMaxDynamicSharedMemorySize, GL_SMEM);
    cudaFuncSetAttribute(gemm_ldsm_nt64, cudaFuncAttributeMaxDynamicSharedMemorySize, G64_SMEM);

    // fused QKV projections: all hi-only (1 MMA per site), 3-stage pipeline
    GemmPtrs Pqkv;
    Pqkv.b0 = wqh; Pqkv.b1 = wkh; Pqkv.b2 = wvh;
    Pqkv.c0 = pq;  Pqkv.c1 = pk;  Pqkv.c2 = pv;
    dim3 gq(DIM / 128, NTOK / 128, 3);   // (12, 32, 3)
    gemm_ldsm_nt<<<gq, 256, GL_SMEM>>>(hh, Pqkv);

    int rope_threads = NTOK * NHD * 3 * 8;
    rope_split_kernel<<<rope_threads / 256, 256>>>(pq, pk, xyz, uqh, ukh);

    dim3 vgrid(SS / 64, BB * NHD);
    vtrans_kernel<<<vgrid, 256>>>(pv, uvh);

    cudaFuncSetAttribute(attn_mma_kernel, cudaFuncAttributeMaxDynamicSharedMemorySize, ATT_SMEM_BYTES);
    dim3 agrid(SS / 64, BB * NHD);       // (32, 32) — 64-row tiles, 2 CTAs/SM
    attn_mma_kernel<<<agrid, 128, ATT_SMEM_BYTES>>>(
        uqh, ukh, uvh, (unsigned int*)aoh);

    // O projection: 128x64 tiles -> 768 CTAs, 3-stage pipeline
    dim3 go(DIM / 64, NTOK / 128);       // (24, 32)
    gemm_ldsm_nt64<<<go, 256, G64_SMEM>>>(aoh, woh, out);
}

// round 17
// speedup vs baseline: 1.0346x; 1.0346x over previous
#include <cuda_runtime.h>
#include <cuda_fp16.h>
#include <math_constants.h>
#include <cstdint>

// Problem constants
#define BB   2
#define SS   2048
#define DIM  1536
#define NHD  16
#define HD   96
#define NTOK (BB*SS)            // 4096
#define ATT_SCALE 0.10206207261596575f   // 1/sqrt(96)

// Scratch (device globals; allocation-free). q/k/v intermediates now fp16.
__device__ __half g_qf[NTOK * DIM];
__device__ __half g_kf[NTOK * DIM];
__device__ __half g_vf[NTOK * DIM];

__device__ __half g_h_hi[NTOK * DIM];
__device__ __half g_ao_hi[NTOK * DIM];
__device__ __half g_wq_hi[DIM * DIM];
__device__ __half g_wk_hi[DIM * DIM];
__device__ __half g_wv_hi[DIM * DIM];
__device__ __half g_wo_hi[DIM * DIM];

// Post-RoPE fp16 (q rounded + prescaled by ATT_SCALE; k rounded), f16x2 words
__device__ unsigned int g_qhi[NTOK * DIM / 2];
__device__ unsigned int g_khi[NTOK * DIM / 2];
// V transposed per (b,h): [32][96][2048] fp16 -> words [32][96][1024]
__device__ unsigned int g_vthi[32 * 96 * 1024];

// ---------------------------------------------------------------------------
// helpers
// ---------------------------------------------------------------------------
__device__ __forceinline__ unsigned int pack_f16x2(float lo, float hi) {
    unsigned int r;
    asm("cvt.rn.f16x2.f32 %0, %1, %2;" : "=r"(r) : "f"(hi), "f"(lo));
    return r;
}
__device__ __forceinline__ unsigned int smem_u32(const void* p) {
    unsigned int a;
    asm("{ .reg .u64 t; cvta.to.shared.u64 t, %1; cvt.u32.u64 %0, t; }"
        : "=r"(a) : "l"(p));
    return a;
}

#define MMA_F16(d, a, b) \
  asm volatile("mma.sync.aligned.m16n8k16.row.col.f32.f16.f16.f32 " \
    "{%0,%1,%2,%3}, {%4,%5,%6,%7}, {%8,%9}, {%0,%1,%2,%3};" \
    : "+f"(d[0]), "+f"(d[1]), "+f"(d[2]), "+f"(d[3]) \
    : "r"(a[0]), "r"(a[1]), "r"(a[2]), "r"(a[3]), "r"(b[0]), "r"(b[1]))

#define LDSM4(r0, r1, r2, r3, addr) \
  asm volatile("ldmatrix.sync.aligned.m8n8.x4.shared.b16 {%0,%1,%2,%3}, [%4];" \
    : "=r"(r0), "=r"(r1), "=r"(r2), "=r"(r3) : "r"(addr))

#define CPA16(dst_s, src_g) \
  asm volatile("cp.async.ca.shared.global [%0], [%1], 16;" :: "r"(dst_s), "l"(src_g))
#define CPA16CG(dst_s, src_g) \
  asm volatile("cp.async.cg.shared.global [%0], [%1], 16;" :: "r"(dst_s), "l"(src_g))
#define CP_COMMIT() asm volatile("cp.async.commit_group;" ::: "memory")
#define CP_WAIT0()  asm volatile("cp.async.wait_group 0;" ::: "memory")

// ---------------------------------------------------------------------------
// fp32 -> fp16 round, single tensor (h / activations)
// ---------------------------------------------------------------------------
__global__ void __launch_bounds__(256) round_fp16_kernel(
    const float4* __restrict__ x, unsigned int* __restrict__ hi, int n4)
{
    int i = blockIdx.x * 256 + threadIdx.x;
    if (i >= n4) return;
    float4 v = x[i];
    hi[i*2]   = pack_f16x2(v.x, v.y);
    hi[i*2+1] = pack_f16x2(v.z, v.w);
}

// fp32 -> fp16 round, 4 weight matrices in one launch (grid.y selects)
struct RoundPtrs {
    const float4 *x0, *x1, *x2, *x3;
    unsigned int *o0, *o1, *o2, *o3;
};
__global__ void __launch_bounds__(256) round4_fp16_kernel(RoundPtrs P, int n4)
{
    int i = blockIdx.x * 256 + threadIdx.x;
    if (i >= n4) return;
    int z = blockIdx.y;
    const float4* x = (z == 0) ? P.x0 : (z == 1) ? P.x1 : (z == 2) ? P.x2 : P.x3;
    unsigned int* hi = (z == 0) ? P.o0 : (z == 1) ? P.o1 : (z == 2) ? P.o2 : P.o3;
    float4 v = x[i];
    hi[i*2]   = pack_f16x2(v.x, v.y);
    hi[i*2+1] = pack_f16x2(v.z, v.w);
}

// ---------------------------------------------------------------------------
// ldmatrix tensor-core GEMM: C[m][n] = sum_k A[m][k] * W[n][k]
// CTA 128x128, BK=64, 256 threads, warp 64x32, fp16 hi-only (1 MMA/site).
// Double-buffered. grid.z = QKV fusion. C output: fp16 (packed f16x2 stores).
// ---------------------------------------------------------------------------
#define GL_STAGE 32768     // 2 tiles x 128 rows x 128B (Ahi, Bhi)
#define GL_SMEM  (2 * GL_STAGE)
#define GL_NC    (DIM / 64)   // 24

struct GemmPtrs {
    const __half *b0, *b1, *b2;
    __half *c0, *c1, *c2;
};

__device__ __forceinline__ void gl_prefetch(
    unsigned int stage_base,
    const __half* __restrict__ a_h, const __half* __restrict__ b_h,
    int tid, int koff)
{
    #pragma unroll
    for (int t = 0; t < 2; t++) {
        const __half* s = (t == 0) ? a_h : b_h;
        #pragma unroll
        for (int i = 0; i < 4; i++) {
            int w = tid + 256 * i;          // 0..1023
            int r = w >> 3, cc = w & 7;     // row, 16B chunk
            unsigned int off = r * 128 + cc * 16;
            unsigned int dst = stage_base + t * 16384 + (off ^ ((off >> 3) & 0x70));
            CPA16CG(dst, s + (size_t)r * DIM + koff + cc * 8);
        }
    }
    CP_COMMIT();
}

__global__ void __launch_bounds__(256, 2) gemm_ldsm_nt(
    const __half* __restrict__ Ahi, GemmPtrs P)
{
    extern __shared__ char smraw[];
    const unsigned int sbase = smem_u32(smraw);
    const int tid  = threadIdx.x;
    const int lane = tid & 31;
    const int warp = tid >> 5;
    const int warp_m = warp >> 2;    // 0..1
    const int warp_n = warp & 3;     // 0..3
    const int row0 = blockIdx.y * 128;
    const int col0 = blockIdx.x * 128;
    const int z = blockIdx.z;

    const __half* Whi = (z == 0) ? P.b0 : (z == 1) ? P.b1 : P.b2;
    __half* C = (z == 0) ? P.c0 : (z == 1) ? P.c1 : P.c2;

    const __half* a_h = Ahi + (size_t)row0 * DIM;
    const __half* b_h = Whi + (size_t)col0 * DIM;

    // ldmatrix lane address components
    const int g = lane >> 3, j = lane & 7;
    const unsigned int rA = warp_m * 64 + (g & 1) * 8 + j;   // + mbl*16
    const unsigned int cA = (g >> 1) * 16;                   // + kc*32
    const unsigned int rB = warp_n * 32 + (g >> 1) * 8 + j;  // + nb2*16
    const unsigned int cB = (g & 1) * 16;

    float acc[4][4][4] = {};    // [mbl][nbl][reg]

    gl_prefetch(sbase, a_h, b_h, tid, 0);

    for (int c = 0; c < GL_NC; c++) {
        CP_WAIT0();
        __syncthreads();
        if (c + 1 < GL_NC)
            gl_prefetch(sbase + ((c + 1) & 1) * GL_STAGE, a_h, b_h,
                        tid, (c + 1) * 64);

        const unsigned int stb = sbase + (c & 1) * GL_STAGE;

        #pragma unroll
        for (int kc = 0; kc < 4; kc++) {
            unsigned int ah[4][4];
            #pragma unroll
            for (int mbl = 0; mbl < 4; mbl++) {
                unsigned int off = (rA + mbl * 16) * 128 + cA + kc * 32;
                unsigned int sw = off ^ ((off >> 3) & 0x70);
                LDSM4(ah[mbl][0], ah[mbl][1], ah[mbl][2], ah[mbl][3], stb + sw);
            }
            unsigned int bh[4][2];
            #pragma unroll
            for (int nb2 = 0; nb2 < 2; nb2++) {
                unsigned int off = (rB + nb2 * 16) * 128 + cB + kc * 32;
                unsigned int sw = off ^ ((off >> 3) & 0x70);
                unsigned int r0, r1, r2, r3;
                LDSM4(r0, r1, r2, r3, stb + 16384 + sw);
                bh[2*nb2][0] = r0; bh[2*nb2][1] = r1;
                bh[2*nb2+1][0] = r2; bh[2*nb2+1][1] = r3;
            }
            #pragma unroll
            for (int mbl = 0; mbl < 4; mbl++)
                #pragma unroll
                for (int nbl = 0; nbl < 4; nbl++)
                    MMA_F16(acc[mbl][nbl], ah[mbl], bh[nbl]);
        }
    }

    // fp16 epilogue (packed f16x2 stores)
    #pragma unroll
    for (int mbl = 0; mbl < 4; mbl++) {
        int mrow = row0 + warp_m * 64 + mbl * 16 + (lane >> 2);
        #pragma unroll
        for (int nbl = 0; nbl < 4; nbl++) {
            int ncol = col0 + warp_n * 32 + nbl * 8 + (lane & 3) * 2;
            *(unsigned int*)&C[(size_t)mrow * DIM + ncol] =
                pack_f16x2(acc[mbl][nbl][0], acc[mbl][nbl][1]);
            *(unsigned int*)&C[(size_t)(mrow + 8) * DIM + ncol] =
                pack_f16x2(acc[mbl][nbl][2], acc[mbl][nbl][3]);
        }
    }
}

// ---------------------------------------------------------------------------
// 128x64 tile GEMM variant for the O-projection (fp32 out, double-buffered).
// ---------------------------------------------------------------------------
#define G64_STAGE 24576    // Ahi 16KB + Bhi 8KB
#define G64_SMEM  (2 * G64_STAGE)

__device__ __forceinline__ void g64_prefetch(
    unsigned int stage_base,
    const __half* __restrict__ a_h, const __half* __restrict__ b_h,
    int tid, int koff)
{
    #pragma unroll
    for (int i = 0; i < 4; i++) {
        int w = tid + 256 * i;
        int r = w >> 3, cc = w & 7;
        unsigned int off = r * 128 + cc * 16;
        unsigned int dst = stage_base + (off ^ ((off >> 3) & 0x70));
        CPA16CG(dst, a_h + (size_t)r * DIM + koff + cc * 8);
    }
    #pragma unroll
    for (int i = 0; i < 2; i++) {
        int w = tid + 256 * i;
        int r = w >> 3, cc = w & 7;
        unsigned int off = r * 128 + cc * 16;
        unsigned int dst = stage_base + 16384 + (off ^ ((off >> 3) & 0x70));
        CPA16CG(dst, b_h + (size_t)r * DIM + koff + cc * 8);
    }
    CP_COMMIT();
}

__global__ void __launch_bounds__(256) gemm_ldsm_nt64(
    const __half* __restrict__ Ahi, const __half* __restrict__ Whi,
    float* __restrict__ C)
{
    extern __shared__ char smraw[];
    const unsigned int sbase = smem_u32(smraw);
    const int tid  = threadIdx.x;
    const int lane = tid & 31;
    const int warp = tid >> 5;
    const int warp_m = warp >> 2;
    const int warp_n = warp & 3;
    const int row0 = blockIdx.y * 128;
    const int col0 = blockIdx.x * 64;

    const __half* a_h = Ahi + (size_t)row0 * DIM;
    const __half* b_h = Whi + (size_t)col0 * DIM;

    const int g = lane >> 3, j = lane & 7;
    const unsigned int rA = warp_m * 64 + (g & 1) * 8 + j;
    const unsigned int cA = (g >> 1) * 16;
    const unsigned int rB = warp_n * 16 + (g >> 1) * 8 + j;
    const unsigned int cB = (g & 1) * 16;

    float acc[4][2][4] = {};

    g64_prefetch(sbase, a_h, b_h, tid, 0);

    for (int c = 0; c < GL_NC; c++) {
        CP_WAIT0();
        __syncthreads();
        if (c + 1 < GL_NC)
            g64_prefetch(sbase + ((c + 1) & 1) * G64_STAGE, a_h, b_h,
                         tid, (c + 1) * 64);

        const unsigned int stb = sbase + (c & 1) * G64_STAGE;

        #pragma unroll
        for (int kc = 0; kc < 4; kc++) {
            unsigned int ah[4][4];
            #pragma unroll
            for (int mbl = 0; mbl < 4; mbl++) {
                unsigned int off = (rA + mbl * 16) * 128 + cA + kc * 32;
                unsigned int sw = off ^ ((off >> 3) & 0x70);
                LDSM4(ah[mbl][0], ah[mbl][1], ah[mbl][2], ah[mbl][3], stb + sw);
            }
            unsigned int bh[2][2];
            {
                unsigned int off = rB * 128 + cB + kc * 32;
                unsigned int sw = off ^ ((off >> 3) & 0x70);
                unsigned int r0, r1, r2, r3;
                LDSM4(r0, r1, r2, r3, stb + 16384 + sw);
                bh[0][0] = r0; bh[0][1] = r1;
                bh[1][0] = r2; bh[1][1] = r3;
            }
            #pragma unroll
            for (int mbl = 0; mbl < 4; mbl++)
                #pragma unroll
                for (int nbl = 0; nbl < 2; nbl++)
                    MMA_F16(acc[mbl][nbl], ah[mbl], bh[nbl]);
        }
    }

    #pragma unroll
    for (int mbl = 0; mbl < 4; mbl++) {
        int mrow = row0 + warp_m * 64 + mbl * 16 + (lane >> 2);
        #pragma unroll
        for (int nbl = 0; nbl < 2; nbl++) {
            int ncol = col0 + warp_n * 16 + nbl * 8 + (lane & 3) * 2;
            float2 v0 = make_float2(acc[mbl][nbl][0], acc[mbl][nbl][1]);
            float2 v1 = make_float2(acc[mbl][nbl][2], acc[mbl][nbl][3]);
            *(float2*)&C[(size_t)mrow * DIM + ncol]       = v0;
            *(float2*)&C[(size_t)(mrow + 8) * DIM + ncol] = v1;
        }
    }
}

// ---------------------------------------------------------------------------
// RoPE (fp16 in, fp32 math): q rounded (prescaled), k rounded -> f16x2 words.
// ---------------------------------------------------------------------------
__global__ void __launch_bounds__(256) rope_split_kernel(
    const __half* __restrict__ q, const __half* __restrict__ k,
    const int* __restrict__ xyz,
    unsigned int* __restrict__ qhi, unsigned int* __restrict__ khi)
{
    int idx = blockIdx.x * 256 + threadIdx.x;   // NTOK*16*3*8
    int j2 = idx & 7;
    int p  = (idx >> 3) % 3;
    int th = idx / 24;
    int h  = th & 15;
    int t  = th >> 4;
    if (t >= NTOK) return;

    float pos = (float)xyz[t * 3 + p];
    const float c = 0.83048202372184058696f;   // log2(10000)/16
    int j0 = 2 * j2;
    float s0, c0, s1, c1;
    sincosf(pos * exp2f(-(float)j0 * c), &s0, &c0);
    sincosf(pos * exp2f(-(float)(j0 + 1) * c), &s1, &c1);

    int base = t * DIM + h * HD + p * 32 + j0;
    int wbase = t * (DIM/2) + h * (HD/2) + p * 16 + j2;

    {
        float2 a = __half22float2(*(const __half2*)&q[base]);
        float2 b = __half22float2(*(const __half2*)&q[base + 16]);
        float o1x = (a.x * c0 - b.x * s0) * ATT_SCALE;
        float o1y = (a.y * c1 - b.y * s1) * ATT_SCALE;
        float o2x = (b.x * c0 + a.x * s0) * ATT_SCALE;
        float o2y = (b.y * c1 + a.y * s1) * ATT_SCALE;
        qhi[wbase]     = pack_f16x2(o1x, o1y);
        qhi[wbase + 8] = pack_f16x2(o2x, o2y);
    }
    {
        float2 a = __half22float2(*(const __half2*)&k[base]);
        float2 b = __half22float2(*(const __half2*)&k[base + 16]);
        float o1x = a.x * c0 - b.x * s0;
        float o1y = a.y * c1 - b.y * s1;
        float o2x = b.x * c0 + a.x * s0;
        float o2y = b.y * c1 + a.y * s1;
        khi[wbase]     = pack_f16x2(o1x, o1y);
        khi[wbase + 8] = pack_f16x2(o2x, o2y);
    }
}

// ---------------------------------------------------------------------------
// V transpose (fp16 in, permute only; 256 threads)
// ---------------------------------------------------------------------------
__global__ void __launch_bounds__(256) vtrans_kernel(
    const __half* __restrict__ v, unsigned int* __restrict__ vthi)
{
    __shared__ unsigned short sm[96 * 66];
    const int tid = threadIdx.x;
    const int bh = blockIdx.y;
    const int b = bh >> 4, h = bh & 15;
    const int s0 = blockIdx.x * 64;

    {
        int s = tid >> 2, qtr = tid & 3;
        const __half* src = v + (size_t)(b * SS + s0 + s) * DIM + h * HD + qtr * 24;
        #pragma unroll
        for (int i = 0; i < 3; i++) {
            // 8 halfs per uint4
            uint4 x = *(const uint4*)(src + i * 8);
            int d = qtr * 24 + i * 8;
            const unsigned int w[4] = { x.x, x.y, x.z, x.w };
            #pragma unroll
            for (int t2 = 0; t2 < 4; t2++) {
                sm[(d + 2*t2 + 0) * 66 + s] = (unsigned short)(w[t2] & 0xffff);
                sm[(d + 2*t2 + 1) * 66 + s] = (unsigned short)(w[t2] >> 16);
            }
        }
    }
    __syncthreads();

    #pragma unroll
    for (int i = 0; i < 12; i++) {
        int w = tid + 256 * i;
        int d = w >> 5, j = w & 31;
        unsigned int lo = sm[d * 66 + 2 * j];
        unsigned int hi = sm[d * 66 + 2 * j + 1];
        vthi[(size_t)(bh * 96 + d) * 1024 + (s0 >> 1) + j] = lo | (hi << 16);
    }
}

// ---------------------------------------------------------------------------
// MMA flash attention (fp16: Q/K/V/P all rounded). 64 q-rows per CTA,
// 128 threads (4 warps), 2 CTAs/SM. Output: aohi only.
// ---------------------------------------------------------------------------
#define AKHI 0
#define AVHI 3328
#define ABUF 6784
#define ATT_SMEM_BYTES (2 * ABUF * 4)

__global__ void __launch_bounds__(128, 2) attn_mma_kernel(
    const unsigned int* __restrict__ qhi,
    const unsigned int* __restrict__ khi,
    const unsigned int* __restrict__ vthi,
    unsigned int* __restrict__ aohi)
{
    extern __shared__ unsigned int smw[];
    unsigned int sbase = smem_u32(smw);

    const int tid  = threadIdx.x;
    const int lane = tid & 31;
    const int warp = tid >> 5;
    const int qt = blockIdx.x;
    const int bh = blockIdx.y;
    const int b = bh >> 4, h = bh & 15;
    const int h48 = h * 48;
    const int qrow0 = b * SS + qt * 64;

    unsigned int qh[6][4];
    {
        const unsigned int* qhg = qhi + (size_t)qrow0 * 768 + h48;
        int r0 = warp * 16 + (lane >> 2);
        #pragma unroll
        for (int kb = 0; kb < 6; kb++) {
            int w0 = kb * 8 + (lane & 3);
            qh[kb][0] = qhg[(size_t)r0 * 768 + w0];
            qh[kb][1] = qhg[(size_t)(r0 + 8) * 768 + w0];
            qh[kb][2] = qhg[(size_t)r0 * 768 + w0 + 4];
            qh[kb][3] = qhg[(size_t)(r0 + 8) * 768 + w0 + 4];
        }
    }

    float O[12][4];
    #pragma unroll
    for (int nb = 0; nb < 12; nb++)
        #pragma unroll
        for (int i = 0; i < 4; i++) O[nb][i] = 0.0f;
    float m0 = -CUDART_INF_F, m1 = -CUDART_INF_F, l0 = 0.0f, l1 = 0.0f;

#define PREFETCH(bi, ktv)                                                      \
    {                                                                          \
        int ktok = b * SS + (ktv) * 64;                                        \
        _Pragma("unroll")                                                      \
        for (int i = 0; i < 6; i++) {                                          \
            int cc = tid + 128 * i;                                            \
            int key = cc / 12, j = cc - key * 12;                              \
            unsigned int dw = ((bi) * ABUF + key * 52 + j * 4);                \
            CPA16(sbase + dw * 4,                                              \
                  khi + (size_t)(ktok + key) * 768 + h48 + j * 4);             \
        }                                                                      \
        _Pragma("unroll")                                                      \
        for (int i = 0; i < 6; i++) {                                          \
            int cc = tid + 128 * i;                                            \
            int d = cc >> 3, j = cc & 7;                                       \
            unsigned int dw = ((bi) * ABUF + AVHI + d * 36 + j * 4);           \
            CPA16(sbase + dw * 4,                                              \
                  vthi + (size_t)(bh * 96 + d) * 1024 + (ktv) * 32 + j * 4);   \
        }                                                                      \
        CP_COMMIT();                                                           \
    }

    PREFETCH(0, 0);

    for (int kt = 0; kt < SS / 64; kt++) {
        CP_WAIT0();
        __syncthreads();
        if (kt + 1 < SS / 64) PREFETCH((kt + 1) & 1, kt + 1);

        const unsigned int* kh = smw + (kt & 1) * ABUF + AKHI;
        const unsigned int* vh = smw + (kt & 1) * ABUF + AVHI;

        float S[8][4];
        #pragma unroll
        for (int nb = 0; nb < 8; nb++) {
            #pragma unroll
            for (int i = 0; i < 4; i++) S[nb][i] = 0.0f;
            int key = nb * 8 + (lane >> 2);
            #pragma unroll
            for (int kb = 0; kb < 6; kb++) {
                int w0 = kb * 8 + (lane & 3);
                unsigned int bhf[2] = { kh[key * 52 + w0], kh[key * 52 + w0 + 4] };
                MMA_F16(S[nb], qh[kb], bhf);
            }
        }

        float ml0 = -CUDART_INF_F, ml1 = -CUDART_INF_F;
        #pragma unroll
        for (int nb = 0; nb < 8; nb++) {
            ml0 = fmaxf(ml0, fmaxf(S[nb][0], S[nb][1]));
            ml1 = fmaxf(ml1, fmaxf(S[nb][2], S[nb][3]));
        }
        ml0 = fmaxf(ml0, __shfl_xor_sync(0xffffffffu, ml0, 1));
        ml0 = fmaxf(ml0, __shfl_xor_sync(0xffffffffu, ml0, 2));
        ml1 = fmaxf(ml1, __shfl_xor_sync(0xffffffffu, ml1, 1));
        ml1 = fmaxf(ml1, __shfl_xor_sync(0xffffffffu, ml1, 2));
        float mn0 = fmaxf(m0, ml0), mn1 = fmaxf(m1, ml1);
        float sc0 = __expf(m0 - mn0), sc1 = __expf(m1 - mn1);
        float r0 = 0.0f, r1 = 0.0f;
        #pragma unroll
        for (int nb = 0; nb < 8; nb++) {
            S[nb][0] = __expf(S[nb][0] - mn0);
            S[nb][1] = __expf(S[nb][1] - mn0);
            S[nb][2] = __expf(S[nb][2] - mn1);
            S[nb][3] = __expf(S[nb][3] - mn1);
            r0 += S[nb][0] + S[nb][1];
            r1 += S[nb][2] + S[nb][3];
        }
        r0 += __shfl_xor_sync(0xffffffffu, r0, 1);
        r0 += __shfl_xor_sync(0xffffffffu, r0, 2);
        r1 += __shfl_xor_sync(0xffffffffu, r1, 1);
        r1 += __shfl_xor_sync(0xffffffffu, r1, 2);
        l0 = l0 * sc0 + r0;  m0 = mn0;
        l1 = l1 * sc1 + r1;  m1 = mn1;

        #pragma unroll
        for (int nb = 0; nb < 12; nb++) {
            O[nb][0] *= sc0; O[nb][1] *= sc0;
            O[nb][2] *= sc1; O[nb][3] *= sc1;
        }

        // P: C-frag -> fp16 A-frag (hi only)
        unsigned int ph[4][4];
        #pragma unroll
        for (int kb = 0; kb < 4; kb++) {
            float f[8] = { S[2*kb][0], S[2*kb][1], S[2*kb][2], S[2*kb][3],
                           S[2*kb+1][0], S[2*kb+1][1], S[2*kb+1][2], S[2*kb+1][3] };
            #pragma unroll
            for (int rgp = 0; rgp < 4; rgp++)
                ph[kb][rgp] = pack_f16x2(f[2*rgp], f[2*rgp+1]);
        }

        #pragma unroll
        for (int nb = 0; nb < 12; nb++) {
            int d = nb * 8 + (lane >> 2);
            #pragma unroll
            for (int kb = 0; kb < 4; kb++) {
                int w0 = kb * 8 + (lane & 3);
                unsigned int bhf[2] = { vh[d * 36 + w0], vh[d * 36 + w0 + 4] };
                MMA_F16(O[nb], ph[kb], bhf);
            }
        }
    }

    float li0 = 1.0f / l0, li1 = 1.0f / l1;
    int tok0 = qrow0 + warp * 16 + (lane >> 2);
    int tok1 = tok0 + 8;
    #pragma unroll
    for (int nb = 0; nb < 12; nb++) {
        int wd = nb * 4 + (lane & 3);
        aohi[(size_t)tok0 * 768 + h48 + wd] =
            pack_f16x2(O[nb][0] * li0, O[nb][1] * li0);
        aohi[(size_t)tok1 * 768 + h48 + wd] =
            pack_f16x2(O[nb][2] * li1, O[nb][3] * li1);
    }
}

// ---------------------------------------------------------------------------
extern "C" void kernel_launch(void* const* d_in, const int* in_sizes, int n_in,
                              void* d_out, int out_size)
{
    const int*   xyz = (const int*)d_in[0];
    const float* h   = (const float*)d_in[1];
    const float* wq  = (const float*)d_in[2];
    const float* wk  = (const float*)d_in[3];
    const float* wv  = (const float*)d_in[4];
    const float* wo  = (const float*)d_in[5];
    float* out = (float*)d_out;

    __half *pq, *pk, *pv;
    cudaGetSymbolAddress((void**)&pq,  g_qf);
    cudaGetSymbolAddress((void**)&pk,  g_kf);
    cudaGetSymbolAddress((void**)&pv,  g_vf);

    __half *hh, *aoh, *wqh, *wkh, *wvh, *woh;
    cudaGetSymbolAddress((void**)&hh,  g_h_hi);
    cudaGetSymbolAddress((void**)&aoh, g_ao_hi);
    cudaGetSymbolAddress((void**)&wqh, g_wq_hi);
    cudaGetSymbolAddress((void**)&wkh, g_wk_hi);
    cudaGetSymbolAddress((void**)&wvh, g_wv_hi);
    cudaGetSymbolAddress((void**)&woh, g_wo_hi);

    unsigned int *uqh, *ukh, *uvh;
    cudaGetSymbolAddress((void**)&uqh, g_qhi);
    cudaGetSymbolAddress((void**)&ukh, g_khi);
    cudaGetSymbolAddress((void**)&uvh, g_vthi);

    const int nH4 = NTOK * DIM / 4;
    const int nW4 = DIM * DIM / 4;
    round_fp16_kernel<<<(nH4 + 255)/256, 256>>>((const float4*)h,
        (unsigned int*)hh, nH4);

    RoundPtrs Rp;
    Rp.x0 = (const float4*)wq; Rp.o0 = (unsigned int*)wqh;
    Rp.x1 = (const float4*)wk; Rp.o1 = (unsigned int*)wkh;
    Rp.x2 = (const float4*)wv; Rp.o2 = (unsigned int*)wvh;
    Rp.x3 = (const float4*)wo; Rp.o3 = (unsigned int*)woh;
    dim3 rg((nW4 + 255)/256, 4);
    round4_fp16_kernel<<<rg, 256>>>(Rp, nW4);

    cudaFuncSetAttribute(gemm_ldsm_nt, cudaFuncAttributeMaxDynamicSharedMemorySize, GL_SMEM);
    cudaFuncSetAttribute(gemm_ldsm_nt64, cudaFuncAttributeMaxDynamicSharedMemorySize, G64_SMEM);

    // fused QKV projections: fp16 in, fp16 out (1 MMA per site)
    GemmPtrs Pqkv;
    Pqkv.b0 = wqh; Pqkv.b1 = wkh; Pqkv.b2 = wvh;
    Pqkv.c0 = pq;  Pqkv.c1 = pk;  Pqkv.c2 = pv;
    dim3 gq(DIM / 128, NTOK / 128, 3);   // (12, 32, 3)
    gemm_ldsm_nt<<<gq, 256, GL_SMEM>>>(hh, Pqkv);

    int rope_threads = NTOK * NHD * 3 * 8;
    rope_split_kernel<<<rope_threads / 256, 256>>>(pq, pk, xyz, uqh, ukh);

    dim3 vgrid(SS / 64, BB * NHD);
    vtrans_kernel<<<vgrid, 256>>>(pv, uvh);

    cudaFuncSetAttribute(attn_mma_kernel, cudaFuncAttributeMaxDynamicSharedMemorySize, ATT_SMEM_BYTES);
    dim3 agrid(SS / 64, BB * NHD);       // (32, 32) — 64-row tiles, 2 CTAs/SM
    attn_mma_kernel<<<agrid, 128, ATT_SMEM_BYTES>>>(
        uqh, ukh, uvh, (unsigned int*)aoh);

    // O projection: 128x64 tiles -> 768 CTAs
    dim3 go(DIM / 64, NTOK / 128);       // (24, 32)
    gemm_ldsm_nt64<<<go, 256, G64_SMEM>>>(aoh, woh, out);
}